// round 11
// baseline (speedup 1.0000x reference)
#include <cuda_runtime.h>
#include <cuda.h>
#include <cuda_fp16.h>
#include <math.h>
#include <stdint.h>

// ---------------- problem constants ----------------
#define HDIM  1024
#define BSZ   4096
#define TLEN  128
#define NGATE 4096            // 4 gates x HDIM, interleaved n' = j*4 + g
#define MT    256
#define NT    256
#define KC    64              // K chunk (elems) = 128B rows, SW128
#define NCHUNK 16             // per n-tile
#define NSTAGE 3
#define JT    16
#define NTHREADS 320          // w0 MMA, w1 TMA, w2-9 epilogue

#if defined(__CUDA_ARCH__) && (defined(__CUDA_ARCH_FEAT_SM103_ALL) || defined(__CUDA_ARCH_FEAT_SM100_ALL) || defined(__CUDA_ARCH_FEAT_SM101_ALL))
#define HAS_TCGEN05 1
#else
#define HAS_TCGEN05 0
#endif

// ---------------- persistent device state ----------------
__device__ __align__(1024) __half g_A[2][(size_t)BSZ * HDIM];  // h fp16 (ping-pong)
__device__ __align__(1024) __half g_Bp[(size_t)NGATE * HDIM];  // weights fp16, gate-interleaved
__device__ float g_c[(size_t)BSZ * HDIM];
__device__ float g_biasp[NGATE];
__device__ float g_wihp[NGATE];
__device__ float g_woutp[HDIM];
__device__ float g_partial[2][(size_t)BSZ * JT];               // double-buffered

// ---------------- smem layout ----------------
#define SM_TMEM   0
#define SM_FULL0  64
#define SM_EMPTY0 (SM_FULL0 + 8*NSTAGE)
#define SM_DONE   (SM_EMPTY0 + 8*NSTAGE)
#define SM_STAGE  1024
#define STAGE_BYTES 65536       // A 32K | B 32K
#define OFF_A 0
#define OFF_B 32768
#define DSMEM (SM_STAGE + NSTAGE*STAGE_BYTES)

// idesc: F32 accum, F16 a/b, N=256, M=128
#define MMA_IDESC 0x08400010u

// ---------------- arch-neutral helpers ----------------
__device__ __forceinline__ uint32_t smem_u32(const void* p) {
    uint32_t a;
    asm("{ .reg .u64 t; cvta.to.shared.u64 t, %1; cvt.u32.u64 %0, t; }" : "=r"(a) : "l"(p));
    return a;
}
__device__ __forceinline__ uint32_t elect1() {
    uint32_t r;
    asm volatile("{ .reg .pred p; elect.sync _|p, 0xFFFFFFFF; selp.b32 %0, 1, 0, p; }" : "=r"(r));
    return r;
}
#define MBARRIER_INIT(addr, cnt) \
    asm volatile("mbarrier.init.shared.b64 [%0], %1;" :: "r"((uint32_t)(addr)), "r"((uint32_t)(cnt)) : "memory")
#define MBARRIER_EXPECT_TX(addr, bytes) \
    asm volatile("mbarrier.arrive.expect_tx.shared.b64 _, [%0], %1;" :: "r"((uint32_t)(addr)), "r"((uint32_t)(bytes)) : "memory")
#define MBARRIER_WAIT_PARITY(addr, par) do { \
    uint32_t _m = (uint32_t)(addr); uint32_t _p = (uint32_t)(par); uint32_t _d; \
    asm volatile("{ .reg .pred p; mbarrier.try_wait.parity.acquire.cta.shared::cta.b64 p, [%1], %2; selp.b32 %0,1,0,p; }" \
        : "=r"(_d) : "r"(_m), "r"(_p) : "memory"); \
    if (!_d) { \
        asm volatile("{ .reg .pred P1; WL_%=: mbarrier.try_wait.parity.acquire.cta.shared::cta.b64 P1, [%0], %1, 0x989680; @P1 bra.uni WD_%=; bra.uni WL_%=; WD_%=: }" \
            :: "r"(_m), "r"(_p) : "memory"); \
    } } while (0)
__device__ __forceinline__ void tma2d(uint32_t dst, const void* tmap, int x, int y, uint32_t mbar) {
    asm volatile("cp.async.bulk.tensor.2d.shared::cta.global.tile.mbarrier::complete_tx::bytes "
                 "[%0], [%1, {%2, %3}], [%4];"
                 :: "r"(dst), "l"(tmap), "r"(x), "r"(y), "r"(mbar) : "memory");
}
// PDL (sm_90+; legal in both PTX passes)
#define PDL_TRIGGER() asm volatile("griddepcontrol.launch_dependents;" ::: "memory")
#define PDL_WAIT()    asm volatile("griddepcontrol.wait;" ::: "memory")
#define PREFETCH_L1(p) asm volatile("prefetch.global.L1 [%0];" :: "l"(p))

// SW128 K-major smem descriptor: layout 2, version 1, SBO=64, LBO=1
static __device__ __forceinline__ uint64_t make_desc_sw128(uint32_t addr) {
    const uint64_t base = (uint64_t(2) << 61) | (uint64_t(1) << 46) | (uint64_t(64) << 32) | (uint64_t(1) << 16);
    return base | ((uint64_t)(addr >> 4) & 0x3FFF);
}

// ---------------- tcgen05 (sm_103a-only PTX pass) ----------------
#if HAS_TCGEN05
#define TCGEN05_ALLOC(sa, n) \
    asm volatile("tcgen05.alloc.cta_group::1.sync.aligned.shared::cta.b32 [%0], %1;" :: "r"((uint32_t)(sa)), "r"((uint32_t)(n)) : "memory")
#define TCGEN05_DEALLOC(t, n) \
    asm volatile("tcgen05.dealloc.cta_group::1.sync.aligned.b32 %0, %1;" :: "r"(t), "r"((uint32_t)(n)))
#define TCGEN05_RELINQUISH() \
    asm volatile("tcgen05.relinquish_alloc_permit.cta_group::1.sync.aligned;")
#define TCGEN05_COMMIT(mb) \
    asm volatile("tcgen05.commit.cta_group::1.mbarrier::arrive::one.shared::cluster.b64 [%0];" :: "r"((uint32_t)(mb)) : "memory")
#define TCGEN05_FENCE_AFTER()  asm volatile("tcgen05.fence::after_thread_sync;" ::: "memory")
#define TCGEN05_WAIT_LD()      asm volatile("tcgen05.wait::ld.sync.aligned;" ::: "memory")

#define TCGEN05_LD_X32(r, ta) \
    asm volatile("tcgen05.ld.sync.aligned.32x32b.x32.b32 " \
        "{%0,%1,%2,%3,%4,%5,%6,%7,%8,%9,%10,%11,%12,%13,%14,%15," \
        "%16,%17,%18,%19,%20,%21,%22,%23,%24,%25,%26,%27,%28,%29,%30,%31}, [%32];" \
        : "=r"((r)[0]),"=r"((r)[1]),"=r"((r)[2]),"=r"((r)[3]),"=r"((r)[4]),"=r"((r)[5]),"=r"((r)[6]),"=r"((r)[7]), \
          "=r"((r)[8]),"=r"((r)[9]),"=r"((r)[10]),"=r"((r)[11]),"=r"((r)[12]),"=r"((r)[13]),"=r"((r)[14]),"=r"((r)[15]), \
          "=r"((r)[16]),"=r"((r)[17]),"=r"((r)[18]),"=r"((r)[19]),"=r"((r)[20]),"=r"((r)[21]),"=r"((r)[22]),"=r"((r)[23]), \
          "=r"((r)[24]),"=r"((r)[25]),"=r"((r)[26]),"=r"((r)[27]),"=r"((r)[28]),"=r"((r)[29]),"=r"((r)[30]),"=r"((r)[31]) \
        : "r"(ta))

__device__ __forceinline__ void mma_f16_ss(uint32_t d, uint64_t ad, uint64_t bd, uint32_t en) {
    asm volatile(
        "{ .reg .pred p; setp.ne.u32 p, %4, 0;\n\t"
        "tcgen05.mma.cta_group::1.kind::f16 [%0], %1, %2, %3, {%5,%5,%5,%5}, p; }"
        :: "r"(d), "l"(ad), "l"(bd), "r"(MMA_IDESC), "r"(en), "r"(0u) : "memory");
}
#endif

// ---------------- prep kernels ----------------
__global__ void prep_weights(const float* __restrict__ W_ih, const float* __restrict__ W_hh,
                             const float* __restrict__ b_ih, const float* __restrict__ b_hh,
                             const float* __restrict__ W_out,
                             __half* __restrict__ Bp, float* __restrict__ biasp,
                             float* __restrict__ wihp, float* __restrict__ woutp)
{
    int idx = blockIdx.x * blockDim.x + threadIdx.x;
    if (idx >= NGATE * HDIM) return;
    int np = idx / HDIM, k = idx - np * HDIM;
    int gg = np & 3, j = np >> 2;
    int src = gg * HDIM + j;
    Bp[(size_t)np * HDIM + k] = __float2half_rn(W_hh[(size_t)src * HDIM + k]);
    if (k == 0) { biasp[np] = b_ih[src] + b_hh[src]; wihp[np] = W_ih[src]; }
    if (np == 0) woutp[k] = W_out[k];
}

__global__ void prep_state(const float* __restrict__ hidden, const float* __restrict__ cell,
                           __half* __restrict__ A0, float* __restrict__ cbuf)
{
    int idx = blockIdx.x * blockDim.x + threadIdx.x;
    if (idx >= BSZ * HDIM) return;
    A0[idx] = __float2half_rn(hidden[idx]);
    cbuf[idx] = cell[idx];
}

#if HAS_TCGEN05
// LSTM pointwise for one 32-col chunk in r[32]. Vectorized param loads +
// batched reciprocals (one RCP per 4 gates; one per 2 tanh(c)).
__device__ __forceinline__ float epi_math(
    const uint32_t* __restrict__ r, int nbase, int jb, float xb,
    float* __restrict__ cbuf, __half* __restrict__ Aout,
    const float* __restrict__ biasp, const float* __restrict__ wihp,
    const float* __restrict__ woutp, size_t mrow, size_t arow)
{
    const float4 ca  = *(const float4*)(cbuf + mrow + jb);
    const float4 cb2 = *(const float4*)(cbuf + mrow + jb + 4);
    float cold[8] = {ca.x, ca.y, ca.z, ca.w, cb2.x, cb2.y, cb2.z, cb2.w};
    float c2s[8], sos[8];
#pragma unroll
    for (int jl = 0; jl < 8; jl++) {
        const int nn = nbase + jl * 4;
        const float4 bs = *(const float4*)(biasp + nn);   // 16B aligned (nn % 4 == 0)
        const float4 ws = *(const float4*)(wihp + nn);
        const float iv = __uint_as_float(r[jl * 4 + 0]) + fmaf(xb, ws.x, bs.x);
        const float fv = __uint_as_float(r[jl * 4 + 1]) + fmaf(xb, ws.y, bs.y);
        const float gv = __uint_as_float(r[jl * 4 + 2]) + fmaf(xb, ws.z, bs.z);
        const float ov = __uint_as_float(r[jl * 4 + 3]) + fmaf(xb, ws.w, bs.w);
        const float ei = __expf(-iv);
        const float ef = __expf(-fv);
        const float eg = __expf(-2.0f * gv);
        const float eo = __expf(-ov);
        const float a = 1.0f + ei, b = 1.0f + ef, cq = 1.0f + eo, d = 1.0f + eg;
        const float ab = a * b, cd = cq * d;
        const float rr = __fdividef(1.0f, ab * cd);     // one RCP for 4 gates
        const float si   = rr * (b * cd);
        const float sf   = rr * (a * cd);
        const float so   = rr * (ab * d);
        const float invd = rr * (ab * cq);
        const float tg = (1.0f - eg) * invd;            // tanh(g)
        c2s[jl] = sf * cold[jl] + si * tg;
        sos[jl] = so;
    }
    const float4 w0 = *(const float4*)(woutp + jb);
    const float4 w1 = *(const float4*)(woutp + jb + 4);
    const float wo[8] = {w0.x, w0.y, w0.z, w0.w, w1.x, w1.y, w1.z, w1.w};
    union { __half h[8]; uint4 v; } Uhi;
    float psum = 0.0f;
#pragma unroll
    for (int p = 0; p < 4; p++) {
        const float e0 = __expf(-2.0f * c2s[2 * p]);
        const float e1 = __expf(-2.0f * c2s[2 * p + 1]);
        const float q0 = 1.0f + e0, q1 = 1.0f + e1;
        const float rr = __fdividef(1.0f, q0 * q1);     // one RCP for 2 tanh(c)
        const float tc0 = (1.0f - e0) * (rr * q1);
        const float tc1 = (1.0f - e1) * (rr * q0);
        const float hn0 = sos[2 * p] * tc0;
        const float hn1 = sos[2 * p + 1] * tc1;
        Uhi.h[2 * p]     = __float2half_rn(hn0);
        Uhi.h[2 * p + 1] = __float2half_rn(hn1);
        psum = fmaf(hn0, wo[2 * p], psum);
        psum = fmaf(hn1, wo[2 * p + 1], psum);
    }
    *(float4*)(cbuf + mrow + jb)     = make_float4(c2s[0], c2s[1], c2s[2], c2s[3]);
    *(float4*)(cbuf + mrow + jb + 4) = make_float4(c2s[4], c2s[5], c2s[6], c2s[7]);
    *(uint4*)(Aout + arow + jb) = Uhi.v;
    return psum;
}
#endif

// ---------------- single-wave fused LSTM step (PDL + prefetch) ----------------
__global__ void __launch_bounds__(NTHREADS, 1)
lstm_step_tma(const __grid_constant__ CUtensorMap tmA,
              const __grid_constant__ CUtensorMap tmB,
              __half* __restrict__ Aout, float* __restrict__ cbuf,
              const float* __restrict__ biasp, const float* __restrict__ wihp,
              const float* __restrict__ woutp,
              const float* __restrict__ partial_prev, float* __restrict__ partial,
              const float* __restrict__ b_out, float* __restrict__ out,
              int t, int use_x)
{
#if HAS_TCGEN05
    extern __shared__ char smem[];
    const uint32_t sbase = smem_u32(smem);
    const int tid = threadIdx.x, wid = tid >> 5, lid = tid & 31;
    const int mx = blockIdx.x & 15, ng = blockIdx.x >> 4;   // 16 m-bands x 8 n-groups
    const int m0 = mx * MT;

    if (tid == 0) {
#pragma unroll
        for (int s = 0; s < NSTAGE; s++) {
            MBARRIER_INIT(sbase + SM_FULL0 + 8 * s, 1);
            MBARRIER_INIT(sbase + SM_EMPTY0 + 8 * s, 1);
        }
        MBARRIER_INIT(sbase + SM_DONE, 1);
    }
    if (wid == 0) TCGEN05_ALLOC(sbase + SM_TMEM, 512);
    __syncthreads();
    uint32_t tmem;
    asm volatile("ld.shared.b32 %0, [%1];" : "=r"(tmem) : "r"(sbase + SM_TMEM));

    if (wid == 0) {
        // ================= MMA warp =================
        TCGEN05_RELINQUISH();
        uint64_t dA[NSTAGE], dB[NSTAGE];
#pragma unroll
        for (int s = 0; s < NSTAGE; s++) {
            const uint32_t aT = sbase + SM_STAGE + s * STAGE_BYTES;
            dA[s] = make_desc_sw128(aT + OFF_A);
            dB[s] = make_desc_sw128(aT + OFF_B);
        }
        int s = 0, ph = 0;
        for (int tile = 0; tile < 2; tile++) {
            asm volatile("bar.sync 1, 288;");          // wait epilogue TMEM drain
            for (int c = 0; c < NCHUNK; c++) {
                MBARRIER_WAIT_PARITY(sbase + SM_FULL0 + 8 * s, ph);
                if (elect1()) {
#pragma unroll
                    for (int kk = 0; kk < 4; kk++) {
                        const uint32_t en0 = (c == 0 && kk == 0) ? 0u : 1u;
                        // rows 128..255 of A tile: +128 rows * 128B = 16KB = 1024 desc units
                        mma_f16_ss(tmem + 0,   dA[s] + kk * 2,        dB[s] + kk * 2, en0);
                        mma_f16_ss(tmem + 256, dA[s] + 1024 + kk * 2, dB[s] + kk * 2, en0);
                    }
                    TCGEN05_COMMIT(sbase + SM_EMPTY0 + 8 * s);
                }
                if (++s == NSTAGE) { s = 0; ph ^= 1; }
            }
            if (elect1()) TCGEN05_COMMIT(sbase + SM_DONE);
        }
        PDL_TRIGGER();
    } else if (wid == 1) {
        // ================= TMA producer warp =================
        if (elect1()) {
            // B (weights) for the first NSTAGE stages has NO dependency on the
            // previous step — issue before the PDL wait.
#pragma unroll
            for (int s = 0; s < NSTAGE; s++) {
                const uint32_t sT = sbase + SM_STAGE + s * STAGE_BYTES;
                const uint32_t fb = sbase + SM_FULL0 + 8 * s;
                MBARRIER_EXPECT_TX(fb, STAGE_BYTES);
                tma2d(sT + OFF_B, &tmB, s * KC, ng * NT, fb);
            }
            PDL_WAIT();     // A (prev step's h) now safe to read
#pragma unroll
            for (int s = 0; s < NSTAGE; s++) {
                const uint32_t sT = sbase + SM_STAGE + s * STAGE_BYTES;
                tma2d(sT + OFF_A, &tmA, s * KC, m0, sbase + SM_FULL0 + 8 * s);
            }
            for (int cc = NSTAGE; cc < 2 * NCHUNK; cc++) {
                const int s = cc % NSTAGE;
                const int par = ((cc / NSTAGE) & 1) ^ 1;
                MBARRIER_WAIT_PARITY(sbase + SM_EMPTY0 + 8 * s, par);
                const uint32_t sT = sbase + SM_STAGE + s * STAGE_BYTES;
                const uint32_t fb = sbase + SM_FULL0 + 8 * s;
                const int c = cc & (NCHUNK - 1);
                const int n0t = (ng + (cc >> 4) * 8) * NT;
                MBARRIER_EXPECT_TX(fb, STAGE_BYTES);
                tma2d(sT + OFF_A, &tmA, c * KC, m0,  fb);
                tma2d(sT + OFF_B, &tmB, c * KC, n0t, fb);
            }
        }
        PDL_TRIGGER();
    } else {
        // ================= epilogue warps (w2-9) =================
        const int sp = wid & 3;
        const int half = (wid >= 6) ? 1 : 0;
        const int m = m0 + half * 128 + sp * 32 + lid;
        const size_t mrow = (size_t)m * HDIM;
        const size_t arow = (size_t)m * HDIM;

        asm volatile("bar.arrive 1, 288;");            // pre-arm drain for tile 0

        PDL_WAIT();  // prev grid done: partial_prev / cbuf reads + prefetches safe

        // feedback pred-reduce (overlaps tile-0 MMA)
        float xb = 0.0f;
        if (use_x) {
            float s = b_out[0];
            const float4* pp = (const float4*)(partial_prev + (size_t)m * JT);
#pragma unroll
            for (int i = 0; i < 4; i++) {
                float4 p = pp[i];
                s += p.x + p.y + p.z + p.w;
            }
            xb = s;
            if (ng == 0) out[(size_t)m * TLEN + (t - 1)] = s;
        }

        // prefetch epilogue working set for both tiles (hidden under MMA)
#pragma unroll
        for (int tl = 0; tl < 2; tl++) {
            const int n0p = (ng + tl * 8) * NT;
            const int j0p = n0p >> 2;
            PREFETCH_L1(cbuf + mrow + j0p);
            PREFETCH_L1(cbuf + mrow + j0p + 32);
            if (lid < 8) {
                PREFETCH_L1(biasp + n0p + lid * 32);
                PREFETCH_L1(wihp + n0p + lid * 32);
            }
            if (lid >= 30) PREFETCH_L1(woutp + j0p + (lid - 30) * 32);
        }

        const uint32_t dbase = tmem + half * 256;
#pragma unroll 1
        for (int tile = 0; tile < 2; tile++) {
            MBARRIER_WAIT_PARITY(sbase + SM_DONE, tile);
            TCGEN05_FENCE_AFTER();
            if (tile == 1) PDL_TRIGGER();              // next kernel may spin up
            const int nt = ng + tile * 8;
            const int n0t = nt * NT, j0t = n0t >> 2;
            float psum = 0.0f;
            uint32_t ra[64], rb[32];
            // pipelined LDTM: all TMEM reads complete BEFORE last 3 math blocks,
            // so the MMA release fires early and tile-1 MMA overlaps the tail.
            TCGEN05_LD_X32(ra,      dbase + 0);
            TCGEN05_LD_X32(ra + 32, dbase + 32);
            TCGEN05_LD_X32(rb,      dbase + 64);
            TCGEN05_WAIT_LD();
            psum += epi_math(ra,      n0t + 0,  j0t + 0, xb, cbuf, Aout, biasp, wihp, woutp, mrow, arow);
            psum += epi_math(ra + 32, n0t + 32, j0t + 8, xb, cbuf, Aout, biasp, wihp, woutp, mrow, arow);
            TCGEN05_LD_X32(ra,      dbase + 96);
            TCGEN05_LD_X32(ra + 32, dbase + 128);
            TCGEN05_WAIT_LD();
            psum += epi_math(rb, n0t + 64, j0t + 16, xb, cbuf, Aout, biasp, wihp, woutp, mrow, arow);
            TCGEN05_LD_X32(rb, dbase + 160);
            TCGEN05_WAIT_LD();
            psum += epi_math(ra,      n0t + 96,  j0t + 24, xb, cbuf, Aout, biasp, wihp, woutp, mrow, arow);
            psum += epi_math(ra + 32, n0t + 128, j0t + 32, xb, cbuf, Aout, biasp, wihp, woutp, mrow, arow);
            TCGEN05_LD_X32(ra,      dbase + 192);
            TCGEN05_LD_X32(ra + 32, dbase + 224);
            TCGEN05_WAIT_LD();
            if (tile == 0) asm volatile("bar.arrive 1, 288;");  // release MMA for tile 1
            psum += epi_math(rb,      n0t + 160, j0t + 40, xb, cbuf, Aout, biasp, wihp, woutp, mrow, arow);
            psum += epi_math(ra,      n0t + 192, j0t + 48, xb, cbuf, Aout, biasp, wihp, woutp, mrow, arow);
            psum += epi_math(ra + 32, n0t + 224, j0t + 56, xb, cbuf, Aout, biasp, wihp, woutp, mrow, arow);
            partial[(size_t)m * JT + nt] = psum;
        }
    }

    __syncthreads();
    if (wid == 0) TCGEN05_DEALLOC(tmem, 512);
#endif
}

// final column (t = TLEN-1) reduce
__global__ void pred_final(const float* __restrict__ partial, const float* __restrict__ b_out,
                           float* __restrict__ out)
{
    const int b = blockIdx.x * blockDim.x + threadIdx.x;
    if (b < BSZ) {
        float s = b_out[0];
        const float* p = partial + (size_t)b * JT;
#pragma unroll
        for (int i = 0; i < JT; i++) s += p[i];
        out[(size_t)b * TLEN + (TLEN - 1)] = s;
    }
}

// ---------------- launch ----------------
typedef CUresult (*PFN_tmEncode)(CUtensorMap*, CUtensorMapDataType, cuuint32_t, void*,
                                 const cuuint64_t*, const cuuint64_t*, const cuuint32_t*,
                                 const cuuint32_t*, CUtensorMapInterleave, CUtensorMapSwizzle,
                                 CUtensorMapL2promotion, CUtensorMapFloatOOBfill);

extern "C" void kernel_launch(void* const* d_in, const int* in_sizes, int n_in,
                              void* d_out, int out_size)
{
    const float* hidden = (const float*)d_in[0];
    const float* cell   = (const float*)d_in[1];
    const float* W_ih   = (const float*)d_in[2];
    const float* W_hh   = (const float*)d_in[3];
    const float* b_ih   = (const float*)d_in[4];
    const float* b_hh   = (const float*)d_in[5];
    const float* W_out  = (const float*)d_in[6];
    const float* b_out  = (const float*)d_in[7];
    float* out = (float*)d_out;

    __half *Abuf, *Bp;
    float *cbuf, *biasp, *wihp, *woutp, *part;
    cudaGetSymbolAddress((void**)&Abuf,  g_A);
    cudaGetSymbolAddress((void**)&Bp,    g_Bp);
    cudaGetSymbolAddress((void**)&cbuf,  g_c);
    cudaGetSymbolAddress((void**)&biasp, g_biasp);
    cudaGetSymbolAddress((void**)&wihp,  g_wihp);
    cudaGetSymbolAddress((void**)&woutp, g_woutp);
    cudaGetSymbolAddress((void**)&part,  g_partial);

    // tensormaps (host encode via driver entry point; no allocation)
    PFN_tmEncode tmEncode = nullptr;
    cudaDriverEntryPointQueryResult qres;
    cudaGetDriverEntryPoint("cuTensorMapEncodeTiled", (void**)&tmEncode,
                            cudaEnableDefault, &qres);
    const size_t NA = (size_t)BSZ * HDIM;
    CUtensorMap tmA0, tmA1, tmB;
    {
        cuuint64_t dimsA[2] = {HDIM, BSZ};
        cuuint64_t strA[1]  = {HDIM * 2};
        cuuint32_t boxA[2]  = {KC, 256};
        cuuint32_t est[2]   = {1, 1};
        tmEncode(&tmA0, CU_TENSOR_MAP_DATA_TYPE_FLOAT16, 2, (void*)Abuf,
                 dimsA, strA, boxA, est, CU_TENSOR_MAP_INTERLEAVE_NONE,
                 CU_TENSOR_MAP_SWIZZLE_128B, CU_TENSOR_MAP_L2_PROMOTION_L2_128B,
                 CU_TENSOR_MAP_FLOAT_OOB_FILL_NONE);
        tmEncode(&tmA1, CU_TENSOR_MAP_DATA_TYPE_FLOAT16, 2, (void*)(Abuf + NA),
                 dimsA, strA, boxA, est, CU_TENSOR_MAP_INTERLEAVE_NONE,
                 CU_TENSOR_MAP_SWIZZLE_128B, CU_TENSOR_MAP_L2_PROMOTION_L2_128B,
                 CU_TENSOR_MAP_FLOAT_OOB_FILL_NONE);
        cuuint64_t dimsB[2] = {HDIM, NGATE};
        cuuint64_t strB[1]  = {HDIM * 2};
        cuuint32_t boxB[2]  = {KC, 256};
        tmEncode(&tmB, CU_TENSOR_MAP_DATA_TYPE_FLOAT16, 2, (void*)Bp,
                 dimsB, strB, boxB, est, CU_TENSOR_MAP_INTERLEAVE_NONE,
                 CU_TENSOR_MAP_SWIZZLE_128B, CU_TENSOR_MAP_L2_PROMOTION_L2_128B,
                 CU_TENSOR_MAP_FLOAT_OOB_FILL_NONE);
    }

    cudaFuncSetAttribute(lstm_step_tma, cudaFuncAttributeMaxDynamicSharedMemorySize, DSMEM);

    prep_weights<<<(NGATE * HDIM + 255) / 256, 256>>>(W_ih, W_hh, b_ih, b_hh, W_out,
                                                      Bp, biasp, wihp, woutp);
    prep_state<<<(BSZ * HDIM + 255) / 256, 256>>>(hidden, cell, Abuf, cbuf);

    // PDL launch config: each step may launch programmatically after the
    // previous step triggers; in-kernel griddepcontrol.wait guards A/state reads.
    cudaLaunchConfig_t cfg = {};
    cfg.gridDim = dim3(128, 1, 1);
    cfg.blockDim = dim3(NTHREADS, 1, 1);
    cfg.dynamicSmemBytes = DSMEM;
    cfg.stream = 0;
    cudaLaunchAttribute attrs[1];
    attrs[0].id = cudaLaunchAttributeProgrammaticStreamSerialization;
    attrs[0].val.programmaticStreamSerializationAllowed = 1;
    cfg.attrs = attrs;
    cfg.numAttrs = 1;

    const size_t NP = (size_t)BSZ * JT;
    for (int t = 0; t < TLEN; t++) {
        __half* Aout = Abuf + (size_t)((t + 1) & 1) * NA;
        const float* ppart = part + (size_t)((t + 1) & 1) * NP;   // (t-1)&1 == (t+1)&1
        float* cpart = part + (size_t)(t & 1) * NP;
        cudaLaunchKernelEx(&cfg, lstm_step_tma, (t & 1) ? tmA1 : tmA0, tmB,
                           Aout, cbuf, biasp, wihp, woutp,
                           ppart, cpart, b_out, out, t, (t > 0) ? 1 : 0);
    }
    pred_final<<<BSZ / 256, 256>>>(part + (size_t)((TLEN - 1) & 1) * NP, b_out, out);
}

// round 12
// speedup vs baseline: 1.1280x; 1.1280x over previous
#include <cuda_runtime.h>
#include <cuda.h>
#include <cuda_fp16.h>
#include <math.h>
#include <stdint.h>

// ---------------- problem constants ----------------
#define HDIM  1024
#define BSZ   4096
#define TLEN  128
#define NGATE 4096            // 4 gates x HDIM, interleaved n' = j*4 + g
#define MT    256
#define NT    256
#define KC    64              // K chunk (elems) = 128B rows, SW128
#define NCHUNK 16             // per n-tile
#define NSTAGE 3
#define JT2   32              // partial slots: 16 n-tiles x 2 col-halves
#define NTHREADS 576          // w0 MMA, w1 TMA, w2-17 epilogue (16 warps)
#define BAR_CNT 544           // MMA warp + 16 epi warps

#if defined(__CUDA_ARCH__) && (defined(__CUDA_ARCH_FEAT_SM103_ALL) || defined(__CUDA_ARCH_FEAT_SM100_ALL) || defined(__CUDA_ARCH_FEAT_SM101_ALL))
#define HAS_TCGEN05 1
#else
#define HAS_TCGEN05 0
#endif

// ---------------- persistent device state ----------------
__device__ __align__(1024) __half g_A[2][(size_t)BSZ * HDIM];  // h fp16 (ping-pong)
__device__ __align__(1024) __half g_Bp[(size_t)NGATE * HDIM];  // weights fp16, gate-interleaved
__device__ float g_c[(size_t)BSZ * HDIM];
__device__ float g_biasp[NGATE];
__device__ float g_wihp[NGATE];
__device__ float g_woutp[HDIM];
__device__ float g_partial[2][(size_t)BSZ * JT2];              // double-buffered

// ---------------- smem layout ----------------
#define SM_TMEM   0
#define SM_FULL0  64
#define SM_EMPTY0 (SM_FULL0 + 8*NSTAGE)
#define SM_DONE   (SM_EMPTY0 + 8*NSTAGE)
#define SM_STAGE  1024
#define STAGE_BYTES 65536       // A 32K | B 32K
#define OFF_A 0
#define OFF_B 32768
#define DSMEM (SM_STAGE + NSTAGE*STAGE_BYTES)

// idesc: F32 accum, F16 a/b, N=256, M=128
#define MMA_IDESC 0x08400010u

// ---------------- arch-neutral helpers ----------------
__device__ __forceinline__ uint32_t smem_u32(const void* p) {
    uint32_t a;
    asm("{ .reg .u64 t; cvta.to.shared.u64 t, %1; cvt.u32.u64 %0, t; }" : "=r"(a) : "l"(p));
    return a;
}
__device__ __forceinline__ uint32_t elect1() {
    uint32_t r;
    asm volatile("{ .reg .pred p; elect.sync _|p, 0xFFFFFFFF; selp.b32 %0, 1, 0, p; }" : "=r"(r));
    return r;
}
#define MBARRIER_INIT(addr, cnt) \
    asm volatile("mbarrier.init.shared.b64 [%0], %1;" :: "r"((uint32_t)(addr)), "r"((uint32_t)(cnt)) : "memory")
#define MBARRIER_EXPECT_TX(addr, bytes) \
    asm volatile("mbarrier.arrive.expect_tx.shared.b64 _, [%0], %1;" :: "r"((uint32_t)(addr)), "r"((uint32_t)(bytes)) : "memory")
#define MBARRIER_WAIT_PARITY(addr, par) do { \
    uint32_t _m = (uint32_t)(addr); uint32_t _p = (uint32_t)(par); uint32_t _d; \
    asm volatile("{ .reg .pred p; mbarrier.try_wait.parity.acquire.cta.shared::cta.b64 p, [%1], %2; selp.b32 %0,1,0,p; }" \
        : "=r"(_d) : "r"(_m), "r"(_p) : "memory"); \
    if (!_d) { \
        asm volatile("{ .reg .pred P1; WL_%=: mbarrier.try_wait.parity.acquire.cta.shared::cta.b64 P1, [%0], %1, 0x989680; @P1 bra.uni WD_%=; bra.uni WL_%=; WD_%=: }" \
            :: "r"(_m), "r"(_p) : "memory"); \
    } } while (0)
__device__ __forceinline__ void tma2d(uint32_t dst, const void* tmap, int x, int y, uint32_t mbar) {
    asm volatile("cp.async.bulk.tensor.2d.shared::cta.global.tile.mbarrier::complete_tx::bytes "
                 "[%0], [%1, {%2, %3}], [%4];"
                 :: "r"(dst), "l"(tmap), "r"(x), "r"(y), "r"(mbar) : "memory");
}

// SW128 K-major smem descriptor: layout 2, version 1, SBO=64, LBO=1
static __device__ __forceinline__ uint64_t make_desc_sw128(uint32_t addr) {
    const uint64_t base = (uint64_t(2) << 61) | (uint64_t(1) << 46) | (uint64_t(64) << 32) | (uint64_t(1) << 16);
    return base | ((uint64_t)(addr >> 4) & 0x3FFF);
}

// ---------------- tcgen05 (sm_103a-only PTX pass) ----------------
#if HAS_TCGEN05
#define TCGEN05_ALLOC(sa, n) \
    asm volatile("tcgen05.alloc.cta_group::1.sync.aligned.shared::cta.b32 [%0], %1;" :: "r"((uint32_t)(sa)), "r"((uint32_t)(n)) : "memory")
#define TCGEN05_DEALLOC(t, n) \
    asm volatile("tcgen05.dealloc.cta_group::1.sync.aligned.b32 %0, %1;" :: "r"(t), "r"((uint32_t)(n)))
#define TCGEN05_RELINQUISH() \
    asm volatile("tcgen05.relinquish_alloc_permit.cta_group::1.sync.aligned;")
#define TCGEN05_COMMIT(mb) \
    asm volatile("tcgen05.commit.cta_group::1.mbarrier::arrive::one.shared::cluster.b64 [%0];" :: "r"((uint32_t)(mb)) : "memory")
#define TCGEN05_FENCE_AFTER()  asm volatile("tcgen05.fence::after_thread_sync;" ::: "memory")
#define TCGEN05_WAIT_LD()      asm volatile("tcgen05.wait::ld.sync.aligned;" ::: "memory")

#define TCGEN05_LD_X32(r, ta) \
    asm volatile("tcgen05.ld.sync.aligned.32x32b.x32.b32 " \
        "{%0,%1,%2,%3,%4,%5,%6,%7,%8,%9,%10,%11,%12,%13,%14,%15," \
        "%16,%17,%18,%19,%20,%21,%22,%23,%24,%25,%26,%27,%28,%29,%30,%31}, [%32];" \
        : "=r"((r)[0]),"=r"((r)[1]),"=r"((r)[2]),"=r"((r)[3]),"=r"((r)[4]),"=r"((r)[5]),"=r"((r)[6]),"=r"((r)[7]), \
          "=r"((r)[8]),"=r"((r)[9]),"=r"((r)[10]),"=r"((r)[11]),"=r"((r)[12]),"=r"((r)[13]),"=r"((r)[14]),"=r"((r)[15]), \
          "=r"((r)[16]),"=r"((r)[17]),"=r"((r)[18]),"=r"((r)[19]),"=r"((r)[20]),"=r"((r)[21]),"=r"((r)[22]),"=r"((r)[23]), \
          "=r"((r)[24]),"=r"((r)[25]),"=r"((r)[26]),"=r"((r)[27]),"=r"((r)[28]),"=r"((r)[29]),"=r"((r)[30]),"=r"((r)[31]) \
        : "r"(ta))

__device__ __forceinline__ void mma_f16_ss(uint32_t d, uint64_t ad, uint64_t bd, uint32_t en) {
    asm volatile(
        "{ .reg .pred p; setp.ne.u32 p, %4, 0;\n\t"
        "tcgen05.mma.cta_group::1.kind::f16 [%0], %1, %2, %3, {%5,%5,%5,%5}, p; }"
        :: "r"(d), "l"(ad), "l"(bd), "r"(MMA_IDESC), "r"(en), "r"(0u) : "memory");
}
#endif

// ---------------- prep kernels ----------------
__global__ void prep_weights(const float* __restrict__ W_ih, const float* __restrict__ W_hh,
                             const float* __restrict__ b_ih, const float* __restrict__ b_hh,
                             const float* __restrict__ W_out,
                             __half* __restrict__ Bp, float* __restrict__ biasp,
                             float* __restrict__ wihp, float* __restrict__ woutp)
{
    int idx = blockIdx.x * blockDim.x + threadIdx.x;
    if (idx >= NGATE * HDIM) return;
    int np = idx / HDIM, k = idx - np * HDIM;
    int gg = np & 3, j = np >> 2;
    int src = gg * HDIM + j;
    Bp[(size_t)np * HDIM + k] = __float2half_rn(W_hh[(size_t)src * HDIM + k]);
    if (k == 0) { biasp[np] = b_ih[src] + b_hh[src]; wihp[np] = W_ih[src]; }
    if (np == 0) woutp[k] = W_out[k];
}

__global__ void prep_state(const float* __restrict__ hidden, const float* __restrict__ cell,
                           __half* __restrict__ A0, float* __restrict__ cbuf)
{
    int idx = blockIdx.x * blockDim.x + threadIdx.x;
    if (idx >= BSZ * HDIM) return;
    A0[idx] = __float2half_rn(hidden[idx]);
    cbuf[idx] = cell[idx];
}

#if HAS_TCGEN05
// LSTM pointwise for one 32-col chunk in r[32]. Vectorized param loads +
// batched reciprocals (one RCP per 4 gates; one per 2 tanh(c)).
__device__ __forceinline__ float epi_math(
    const uint32_t* __restrict__ r, int nbase, int jb, float xb,
    float* __restrict__ cbuf, __half* __restrict__ Aout,
    const float* __restrict__ biasp, const float* __restrict__ wihp,
    const float* __restrict__ woutp, size_t mrow)
{
    const float4 ca  = *(const float4*)(cbuf + mrow + jb);
    const float4 cb2 = *(const float4*)(cbuf + mrow + jb + 4);
    float cold[8] = {ca.x, ca.y, ca.z, ca.w, cb2.x, cb2.y, cb2.z, cb2.w};
    float c2s[8], sos[8];
#pragma unroll
    for (int jl = 0; jl < 8; jl++) {
        const int nn = nbase + jl * 4;
        const float4 bs = *(const float4*)(biasp + nn);   // 16B aligned
        const float4 ws = *(const float4*)(wihp + nn);
        const float iv = __uint_as_float(r[jl * 4 + 0]) + fmaf(xb, ws.x, bs.x);
        const float fv = __uint_as_float(r[jl * 4 + 1]) + fmaf(xb, ws.y, bs.y);
        const float gv = __uint_as_float(r[jl * 4 + 2]) + fmaf(xb, ws.z, bs.z);
        const float ov = __uint_as_float(r[jl * 4 + 3]) + fmaf(xb, ws.w, bs.w);
        const float ei = __expf(-iv);
        const float ef = __expf(-fv);
        const float eg = __expf(-2.0f * gv);
        const float eo = __expf(-ov);
        const float a = 1.0f + ei, b = 1.0f + ef, cq = 1.0f + eo, d = 1.0f + eg;
        const float ab = a * b, cd = cq * d;
        const float rr = __fdividef(1.0f, ab * cd);     // one RCP for 4 gates
        const float si   = rr * (b * cd);
        const float sf   = rr * (a * cd);
        const float so   = rr * (ab * d);
        const float invd = rr * (ab * cq);
        const float tg = (1.0f - eg) * invd;            // tanh(g)
        c2s[jl] = sf * cold[jl] + si * tg;
        sos[jl] = so;
    }
    const float4 w0 = *(const float4*)(woutp + jb);
    const float4 w1 = *(const float4*)(woutp + jb + 4);
    const float wo[8] = {w0.x, w0.y, w0.z, w0.w, w1.x, w1.y, w1.z, w1.w};
    union { __half h[8]; uint4 v; } Uhi;
    float psum = 0.0f;
#pragma unroll
    for (int p = 0; p < 4; p++) {
        const float e0 = __expf(-2.0f * c2s[2 * p]);
        const float e1 = __expf(-2.0f * c2s[2 * p + 1]);
        const float q0 = 1.0f + e0, q1 = 1.0f + e1;
        const float rr = __fdividef(1.0f, q0 * q1);     // one RCP for 2 tanh(c)
        const float tc0 = (1.0f - e0) * (rr * q1);
        const float tc1 = (1.0f - e1) * (rr * q0);
        const float hn0 = sos[2 * p] * tc0;
        const float hn1 = sos[2 * p + 1] * tc1;
        Uhi.h[2 * p]     = __float2half_rn(hn0);
        Uhi.h[2 * p + 1] = __float2half_rn(hn1);
        psum = fmaf(hn0, wo[2 * p], psum);
        psum = fmaf(hn1, wo[2 * p + 1], psum);
    }
    *(float4*)(cbuf + mrow + jb)     = make_float4(c2s[0], c2s[1], c2s[2], c2s[3]);
    *(float4*)(cbuf + mrow + jb + 4) = make_float4(c2s[4], c2s[5], c2s[6], c2s[7]);
    *(uint4*)(Aout + mrow + jb) = Uhi.v;                // Aout row == mrow (HDIM)
    return psum;
}
#endif

// ---------------- single-wave fused LSTM step (16 epi warps) ----------------
__global__ void __launch_bounds__(NTHREADS, 1)
lstm_step_tma(const __grid_constant__ CUtensorMap tmA,
              const __grid_constant__ CUtensorMap tmB,
              __half* __restrict__ Aout, float* __restrict__ cbuf,
              const float* __restrict__ biasp, const float* __restrict__ wihp,
              const float* __restrict__ woutp,
              const float* __restrict__ partial_prev, float* __restrict__ partial,
              const float* __restrict__ b_out, float* __restrict__ out,
              int t, int use_x)
{
#if HAS_TCGEN05
    extern __shared__ char smem[];
    const uint32_t sbase = smem_u32(smem);
    const int tid = threadIdx.x, wid = tid >> 5, lid = tid & 31;
    const int mx = blockIdx.x & 15, ng = blockIdx.x >> 4;   // 16 m-bands x 8 n-groups
    const int m0 = mx * MT;

    if (tid == 0) {
#pragma unroll
        for (int s = 0; s < NSTAGE; s++) {
            MBARRIER_INIT(sbase + SM_FULL0 + 8 * s, 1);
            MBARRIER_INIT(sbase + SM_EMPTY0 + 8 * s, 1);
        }
        MBARRIER_INIT(sbase + SM_DONE, 1);
    }
    if (wid == 0) TCGEN05_ALLOC(sbase + SM_TMEM, 512);
    __syncthreads();
    uint32_t tmem;
    asm volatile("ld.shared.b32 %0, [%1];" : "=r"(tmem) : "r"(sbase + SM_TMEM));

    if (wid == 0) {
        // ================= MMA warp =================
        TCGEN05_RELINQUISH();
        uint64_t dA[NSTAGE], dB[NSTAGE];
#pragma unroll
        for (int s = 0; s < NSTAGE; s++) {
            const uint32_t aT = sbase + SM_STAGE + s * STAGE_BYTES;
            dA[s] = make_desc_sw128(aT + OFF_A);
            dB[s] = make_desc_sw128(aT + OFF_B);
        }
        int s = 0, ph = 0;
        for (int tile = 0; tile < 2; tile++) {
            asm volatile("bar.sync 1, %0;" :: "n"(BAR_CNT));   // epilogue TMEM drained
            for (int c = 0; c < NCHUNK; c++) {
                MBARRIER_WAIT_PARITY(sbase + SM_FULL0 + 8 * s, ph);
                if (elect1()) {
#pragma unroll
                    for (int kk = 0; kk < 4; kk++) {
                        const uint32_t en0 = (c == 0 && kk == 0) ? 0u : 1u;
                        // rows 128..255 of A tile: +128 rows * 128B = 1024 desc units
                        mma_f16_ss(tmem + 0,   dA[s] + kk * 2,        dB[s] + kk * 2, en0);
                        mma_f16_ss(tmem + 256, dA[s] + 1024 + kk * 2, dB[s] + kk * 2, en0);
                    }
                    TCGEN05_COMMIT(sbase + SM_EMPTY0 + 8 * s);
                }
                if (++s == NSTAGE) { s = 0; ph ^= 1; }
            }
            if (elect1()) TCGEN05_COMMIT(sbase + SM_DONE);
        }
    } else if (wid == 1) {
        // ================= TMA producer warp =================
        if (elect1()) {
            int s = 0, ph = 1;
            for (int cc = 0; cc < 2 * NCHUNK; cc++) {
                MBARRIER_WAIT_PARITY(sbase + SM_EMPTY0 + 8 * s, ph);
                const uint32_t sT = sbase + SM_STAGE + s * STAGE_BYTES;
                const uint32_t fb = sbase + SM_FULL0 + 8 * s;
                const int c = cc & (NCHUNK - 1);
                const int n0t = (ng + (cc >> 4) * 8) * NT;
                MBARRIER_EXPECT_TX(fb, STAGE_BYTES);
                tma2d(sT + OFF_A, &tmA, c * KC, m0,  fb);
                tma2d(sT + OFF_B, &tmB, c * KC, n0t, fb);
                if (++s == NSTAGE) { s = 0; ph ^= 1; }
            }
        }
    } else {
        // ================= epilogue warps (w2-17) =================
        // 16 warps: subpartition k = wid&3 (lanes 32k..32k+31), row-half and
        // column-half split so 2 warps share each lane-set at different cols.
        const int e = wid - 2;
        const int k = wid & 3;
        const int half = (e >> 2) & 1;      // row half (TMEM col block 0/256)
        const int ch = e >> 3;              // column half within the tile
        const int m = m0 + half * 128 + k * 32 + lid;
        const size_t mrow = (size_t)m * HDIM;

        asm volatile("bar.arrive 1, %0;" :: "n"(BAR_CNT));   // pre-arm drain

        // feedback pred-reduce (overlaps tile-0 MMA)
        float xb = 0.0f;
        if (use_x) {
            float s = b_out[0];
            const float4* pp = (const float4*)(partial_prev + (size_t)m * JT2);
#pragma unroll
            for (int i = 0; i < 8; i++) {
                float4 p = pp[i];
                s += p.x + p.y + p.z + p.w;
            }
            xb = s;
            if (ng == 0 && ch == 0) out[(size_t)m * TLEN + (t - 1)] = s;
        }

        const uint32_t dbase = tmem + half * 256 + ch * 128;
#pragma unroll 1
        for (int tile = 0; tile < 2; tile++) {
            MBARRIER_WAIT_PARITY(sbase + SM_DONE, tile);
            TCGEN05_FENCE_AFTER();
            const int nt = ng + tile * 8;
            const int nb = nt * NT + ch * 128;   // this warp's 128-col slice
            const int jb = nb >> 2;
            float psum = 0.0f;
            uint32_t r0[32], r1[32];
            TCGEN05_LD_X32(r0, dbase + 0);
            TCGEN05_LD_X32(r1, dbase + 32);
            TCGEN05_WAIT_LD();
            psum += epi_math(r0, nb + 0,  jb + 0, xb, cbuf, Aout, biasp, wihp, woutp, mrow);
            psum += epi_math(r1, nb + 32, jb + 8, xb, cbuf, Aout, biasp, wihp, woutp, mrow);
            TCGEN05_LD_X32(r0, dbase + 64);
            TCGEN05_LD_X32(r1, dbase + 96);
            TCGEN05_WAIT_LD();
            if (tile == 0) asm volatile("bar.arrive 1, %0;" :: "n"(BAR_CNT)); // release MMA
            psum += epi_math(r0, nb + 64, jb + 16, xb, cbuf, Aout, biasp, wihp, woutp, mrow);
            psum += epi_math(r1, nb + 96, jb + 24, xb, cbuf, Aout, biasp, wihp, woutp, mrow);
            partial[(size_t)m * JT2 + nt * 2 + ch] = psum;
        }
    }

    __syncthreads();
    if (wid == 0) TCGEN05_DEALLOC(tmem, 512);
#endif
}

// final column (t = TLEN-1) reduce
__global__ void pred_final(const float* __restrict__ partial, const float* __restrict__ b_out,
                           float* __restrict__ out)
{
    const int b = blockIdx.x * blockDim.x + threadIdx.x;
    if (b < BSZ) {
        float s = b_out[0];
        const float* p = partial + (size_t)b * JT2;
#pragma unroll
        for (int i = 0; i < JT2; i++) s += p[i];
        out[(size_t)b * TLEN + (TLEN - 1)] = s;
    }
}

// ---------------- launch ----------------
typedef CUresult (*PFN_tmEncode)(CUtensorMap*, CUtensorMapDataType, cuuint32_t, void*,
                                 const cuuint64_t*, const cuuint64_t*, const cuuint32_t*,
                                 const cuuint32_t*, CUtensorMapInterleave, CUtensorMapSwizzle,
                                 CUtensorMapL2promotion, CUtensorMapFloatOOBfill);

extern "C" void kernel_launch(void* const* d_in, const int* in_sizes, int n_in,
                              void* d_out, int out_size)
{
    const float* hidden = (const float*)d_in[0];
    const float* cell   = (const float*)d_in[1];
    const float* W_ih   = (const float*)d_in[2];
    const float* W_hh   = (const float*)d_in[3];
    const float* b_ih   = (const float*)d_in[4];
    const float* b_hh   = (const float*)d_in[5];
    const float* W_out  = (const float*)d_in[6];
    const float* b_out  = (const float*)d_in[7];
    float* out = (float*)d_out;

    __half *Abuf, *Bp;
    float *cbuf, *biasp, *wihp, *woutp, *part;
    cudaGetSymbolAddress((void**)&Abuf,  g_A);
    cudaGetSymbolAddress((void**)&Bp,    g_Bp);
    cudaGetSymbolAddress((void**)&cbuf,  g_c);
    cudaGetSymbolAddress((void**)&biasp, g_biasp);
    cudaGetSymbolAddress((void**)&wihp,  g_wihp);
    cudaGetSymbolAddress((void**)&woutp, g_woutp);
    cudaGetSymbolAddress((void**)&part,  g_partial);

    // tensormaps (host encode via driver entry point; no allocation)
    PFN_tmEncode tmEncode = nullptr;
    cudaDriverEntryPointQueryResult qres;
    cudaGetDriverEntryPoint("cuTensorMapEncodeTiled", (void**)&tmEncode,
                            cudaEnableDefault, &qres);
    const size_t NA = (size_t)BSZ * HDIM;
    CUtensorMap tmA0, tmA1, tmB;
    {
        cuuint64_t dimsA[2] = {HDIM, BSZ};
        cuuint64_t strA[1]  = {HDIM * 2};
        cuuint32_t boxA[2]  = {KC, 256};
        cuuint32_t est[2]   = {1, 1};
        tmEncode(&tmA0, CU_TENSOR_MAP_DATA_TYPE_FLOAT16, 2, (void*)Abuf,
                 dimsA, strA, boxA, est, CU_TENSOR_MAP_INTERLEAVE_NONE,
                 CU_TENSOR_MAP_SWIZZLE_128B, CU_TENSOR_MAP_L2_PROMOTION_L2_128B,
                 CU_TENSOR_MAP_FLOAT_OOB_FILL_NONE);
        tmEncode(&tmA1, CU_TENSOR_MAP_DATA_TYPE_FLOAT16, 2, (void*)(Abuf + NA),
                 dimsA, strA, boxA, est, CU_TENSOR_MAP_INTERLEAVE_NONE,
                 CU_TENSOR_MAP_SWIZZLE_128B, CU_TENSOR_MAP_L2_PROMOTION_L2_128B,
                 CU_TENSOR_MAP_FLOAT_OOB_FILL_NONE);
        cuuint64_t dimsB[2] = {HDIM, NGATE};
        cuuint64_t strB[1]  = {HDIM * 2};
        cuuint32_t boxB[2]  = {KC, 256};
        tmEncode(&tmB, CU_TENSOR_MAP_DATA_TYPE_FLOAT16, 2, (void*)Bp,
                 dimsB, strB, boxB, est, CU_TENSOR_MAP_INTERLEAVE_NONE,
                 CU_TENSOR_MAP_SWIZZLE_128B, CU_TENSOR_MAP_L2_PROMOTION_L2_128B,
                 CU_TENSOR_MAP_FLOAT_OOB_FILL_NONE);
    }

    cudaFuncSetAttribute(lstm_step_tma, cudaFuncAttributeMaxDynamicSharedMemorySize, DSMEM);

    prep_weights<<<(NGATE * HDIM + 255) / 256, 256>>>(W_ih, W_hh, b_ih, b_hh, W_out,
                                                      Bp, biasp, wihp, woutp);
    prep_state<<<(BSZ * HDIM + 255) / 256, 256>>>(hidden, cell, Abuf, cbuf);

    const size_t NP = (size_t)BSZ * JT2;
    for (int t = 0; t < TLEN; t++) {
        __half* Aout = Abuf + (size_t)((t + 1) & 1) * NA;
        const float* ppart = part + (size_t)((t + 1) & 1) * NP;   // (t-1)&1 == (t+1)&1
        float* cpart = part + (size_t)(t & 1) * NP;
        lstm_step_tma<<<128, NTHREADS, DSMEM>>>((t & 1) ? tmA1 : tmA0, tmB,
                                                Aout, cbuf, biasp, wihp, woutp,
                                                ppart, cpart, b_out, out,
                                                t, (t > 0) ? 1 : 0);
    }
    pred_final<<<BSZ / 256, 256>>>(part + (size_t)((TLEN - 1) & 1) * NP, b_out, out);
}